// round 7
// baseline (speedup 1.0000x reference)
#include <cuda_runtime.h>
#include <math.h>

// Problem constants
#define B_    32
#define C_    256
#define L_    8192
#define H_    16
#define ROWS  (B_ * C_)          // 8192
#define L4    (L_ / 4)           // 2048 float4 per row
#define ITER  8                  // 2048 / 256 threads
#define TPB   256
#define TASKS_PER_B (C_ + 1 + C_)      // 513: means, excite, scales
#define NTASKS (B_ * TASKS_PER_B)      // 16416
#define P_BLOCKS (148 * 6)             // persistent grid ≈ resident capacity

// Scratch (allocation-free rule: __device__ globals)
__device__ float d_y[ROWS];
__device__ float d_g[ROWS];
__device__ int   g_task;
__device__ int   g_cnt[B_];
__device__ int   g_flag[B_];

// ---------------------------------------------------------------------------
__global__ void se_init() {
    const int t = threadIdx.x;
    if (t == 0) g_task = 0;
    if (t < B_) { g_cnt[t] = 0; g_flag[t] = 0; }
}

// ---------------------------------------------------------------------------
// Persistent worker: atomic task queue, per-batch [256 mean | 1 excite | 256 scale].
// ---------------------------------------------------------------------------
__global__ __launch_bounds__(TPB, 6) void se_persist(const float4* __restrict__ x,
                                                     float4* __restrict__ out,
                                                     const float* __restrict__ W1,
                                                     const float* __restrict__ W2) {
    __shared__ int   s_task;
    __shared__ float warp_sums[8];
    __shared__ float ys[C_];
    __shared__ float hs[H_];

    const int t    = threadIdx.x;
    const int lane = t & 31;
    const int wid  = t >> 5;

    for (;;) {
        if (t == 0) s_task = atomicAdd(&g_task, 1);
        __syncthreads();
        const int task = s_task;
        if (task >= NTASKS) return;

        const int b = task / TASKS_PER_B;
        const int r = task - b * TASKS_PER_B;

        if (r < C_) {
            // ---- MEAN of row (b, r): 8 MiB/batch read, default policy -> L2 resident
            const int row = b * C_ + r;
            const float4* __restrict__ p = x + (size_t)row * L4;
            float s = 0.0f;
            #pragma unroll
            for (int i = 0; i < ITER; ++i) {
                float4 v = __ldg(p + t + i * 256);
                s += (v.x + v.y) + (v.z + v.w);
            }
            #pragma unroll
            for (int off = 16; off > 0; off >>= 1)
                s += __shfl_xor_sync(0xFFFFFFFFu, s, off);
            if (lane == 0) warp_sums[wid] = s;
            __syncthreads();
            if (wid == 0) {
                float tt = (lane < 8) ? warp_sums[lane] : 0.0f;
                #pragma unroll
                for (int off = 4; off > 0; off >>= 1)
                    tt += __shfl_xor_sync(0xFFFFFFFFu, tt, off);
                if (lane == 0) {
                    d_y[row] = tt * (1.0f / (float)L_);
                    __threadfence();                       // release d_y
                    atomicAdd(&g_cnt[b], 1);
                }
            }
        } else if (r == C_) {
            // ---- EXCITE for batch b: wait for 256 means, compute gates, raise flag
            if (t == 0) {
                while (((volatile int*)g_cnt)[b] < C_) __nanosleep(64);
            }
            __syncthreads();
            __threadfence();                               // acquire
            ys[t] = __ldcg(&d_y[b * C_ + t]);
            __syncthreads();
            {
                const int hh = t >> 4;
                const int k  = t & 15;
                const float* __restrict__ w1 = W1 + hh * C_ + k * 16;
                const float* __restrict__ yy = ys + k * 16;
                float s = 0.0f;
                #pragma unroll
                for (int i = 0; i < 16; ++i) s += yy[i] * w1[i];
                #pragma unroll
                for (int off = 8; off > 0; off >>= 1)
                    s += __shfl_down_sync(0xFFFFFFFFu, s, off, 16);
                if (k == 0) hs[hh] = fmaxf(s, 0.0f);
            }
            __syncthreads();
            {
                float s = 0.0f;
                const float* __restrict__ w2 = W2 + t * H_;
                #pragma unroll
                for (int j = 0; j < H_; ++j) s += hs[j] * w2[j];
                d_g[b * C_ + t] = 1.0f / (1.0f + expf(-s));
            }
            __threadfence();                               // release d_g
            __syncthreads();
            if (t == 0) atomicExch(&g_flag[b], 1);
        } else {
            // ---- SCALE row (b, r-257): wait flag, re-read (L2 hit) * gate, write out
            const int row = b * C_ + (r - C_ - 1);
            if (t == 0) {
                while (((volatile int*)g_flag)[b] == 0) __nanosleep(64);
            }
            __syncthreads();
            __threadfence();                               // acquire
            const float gv = __ldcg(&d_g[row]);

            const float4* __restrict__ px = x   + (size_t)row * L4 + t;
            float4* __restrict__       po = out + (size_t)row * L4 + t;
            #pragma unroll
            for (int g2 = 0; g2 < 2; ++g2) {
                float4 v[4];
                #pragma unroll
                for (int i = 0; i < 4; ++i)
                    v[i] = __ldcs(px + (g2 * 4 + i) * 256);
                #pragma unroll
                for (int i = 0; i < 4; ++i) {
                    v[i].x *= gv; v[i].y *= gv; v[i].z *= gv; v[i].w *= gv;
                    __stcs(po + (g2 * 4 + i) * 256, v[i]);
                }
            }
        }
        __syncthreads();   // protect smem reuse across tasks
    }
}

// ---------------------------------------------------------------------------
extern "C" void kernel_launch(void* const* d_in, const int* in_sizes, int n_in,
                              void* d_out, int out_size) {
    const float4* x  = (const float4*)d_in[0];
    const float*  W1 = (const float*)d_in[1];
    const float*  W2 = (const float*)d_in[2];
    float4* out = (float4*)d_out;

    se_init<<<1, 64>>>();
    se_persist<<<P_BLOCKS, TPB>>>(x, out, W1, W2);
}

// round 8
// speedup vs baseline: 1.3995x; 1.3995x over previous
#include <cuda_runtime.h>
#include <math.h>

// Problem constants
#define B_    32
#define C_    256
#define L_    8192
#define H_    16
#define ROWS  (B_ * C_)          // 8192
#define L4    (L_ / 4)           // 2048 float4 per row
#define ITER  8
#define TPB   256

// Streams: mean-stream = per batch [256 means, 1 excite] = 257*32 = 8224
//          scale-stream = 256*32 = 8192
#define NM    (B_ * (C_ + 1))    // 8224
#define NS    ROWS               // 8192
#define NTASKS (NM + NS)         // 16416
#define LEAD  1028               // 4 batches of mean-stream first
#define ALT_END (LEAD + 2 * (NM - LEAD))   // 1028 + 14392 = 15420
#define P_BLOCKS 888

// Scratch (allocation-free rule: __device__ globals)
__device__ float d_y[ROWS];
__device__ float d_g[ROWS];
__device__ int   g_task;
__device__ int   g_cnt[B_];
__device__ int   g_flag[B_];

// ---------------------------------------------------------------------------
__global__ void se_init() {
    const int t = threadIdx.x;
    if (t == 0) g_task = 0;
    if (t < B_) { g_cnt[t] = 0; g_flag[t] = 0; }
}

// ---------------------------------------------------------------------------
__global__ __launch_bounds__(TPB, 6) void se_persist(const float4* __restrict__ x,
                                                     float4* __restrict__ out,
                                                     const float* __restrict__ W1,
                                                     const float* __restrict__ W2) {
    __shared__ int   s_task;
    __shared__ float warp_sums[8];
    __shared__ float ys[C_];
    __shared__ float hs[H_];

    const int t    = threadIdx.x;
    const int lane = t & 31;
    const int wid  = t >> 5;

    for (;;) {
        if (t == 0) s_task = atomicAdd(&g_task, 1);
        __syncthreads();
        const int task = s_task;
        if (task >= NTASKS) return;

        // ---- map queue position -> (stream, index) ----
        // [0, LEAD): mean-stream. [LEAD, ALT_END): alternate scale/mean.
        // [ALT_END, NTASKS): tail scale-stream.
        int mean_idx = -1, scale_idx = -1;
        if (task < LEAD) {
            mean_idx = task;
        } else if (task < ALT_END) {
            const int j = task - LEAD;
            if (j & 1) mean_idx = LEAD + (j >> 1);
            else       scale_idx = j >> 1;
        } else {
            scale_idx = (NM - LEAD) + (task - ALT_END);
        }

        if (mean_idx >= 0) {
            const int b = mean_idx / (C_ + 1);
            const int r = mean_idx - b * (C_ + 1);
            if (r < C_) {
                // ---- MEAN of row (b, r) ----
                const int row = b * C_ + r;
                const float4* __restrict__ p = x + (size_t)row * L4;
                float s = 0.0f;
                #pragma unroll
                for (int i = 0; i < ITER; ++i) {
                    float4 v = __ldg(p + t + i * 256);
                    s += (v.x + v.y) + (v.z + v.w);
                }
                #pragma unroll
                for (int off = 16; off > 0; off >>= 1)
                    s += __shfl_xor_sync(0xFFFFFFFFu, s, off);
                if (lane == 0) warp_sums[wid] = s;
                __syncthreads();
                if (wid == 0) {
                    float tt = (lane < 8) ? warp_sums[lane] : 0.0f;
                    #pragma unroll
                    for (int off = 4; off > 0; off >>= 1)
                        tt += __shfl_xor_sync(0xFFFFFFFFu, tt, off);
                    if (lane == 0) {
                        d_y[row] = tt * (1.0f / (float)L_);
                        __threadfence();                    // release d_y
                        atomicAdd(&g_cnt[b], 1);
                    }
                }
            } else {
                // ---- EXCITE for batch b (spins at most on trailing in-flight means)
                if (t == 0) {
                    while (((volatile int*)g_cnt)[b] < C_) __nanosleep(32);
                }
                __syncthreads();
                __threadfence();                            // acquire
                ys[t] = __ldcg(&d_y[b * C_ + t]);
                __syncthreads();
                {
                    const int hh = t >> 4;
                    const int k  = t & 15;
                    const float* __restrict__ w1 = W1 + hh * C_ + k * 16;
                    const float* __restrict__ yy = ys + k * 16;
                    float s = 0.0f;
                    #pragma unroll
                    for (int i = 0; i < 16; ++i) s += yy[i] * w1[i];
                    #pragma unroll
                    for (int off = 8; off > 0; off >>= 1)
                        s += __shfl_down_sync(0xFFFFFFFFu, s, off, 16);
                    if (k == 0) hs[hh] = fmaxf(s, 0.0f);
                }
                __syncthreads();
                {
                    float s = 0.0f;
                    const float* __restrict__ w2 = W2 + t * H_;
                    #pragma unroll
                    for (int j = 0; j < H_; ++j) s += hs[j] * w2[j];
                    d_g[b * C_ + t] = 1.0f / (1.0f + expf(-s));
                }
                __threadfence();                            // release d_g
                __syncthreads();
                if (t == 0) atomicExch(&g_flag[b], 1);
            }
        } else {
            // ---- SCALE row scale_idx: excite finished ~1400 queue slots ago ----
            const int row = scale_idx;
            const int b   = row >> 8;
            if (t == 0) {
                while (((volatile int*)g_flag)[b] == 0) __nanosleep(32);
            }
            __syncthreads();
            __threadfence();                                // acquire
            const float gv = __ldcg(&d_g[row]);

            const float4* __restrict__ px = x   + (size_t)row * L4 + t;
            float4* __restrict__       po = out + (size_t)row * L4 + t;
            #pragma unroll
            for (int g2 = 0; g2 < 2; ++g2) {
                float4 v[4];
                #pragma unroll
                for (int i = 0; i < 4; ++i)
                    v[i] = __ldcs(px + (g2 * 4 + i) * 256);
                #pragma unroll
                for (int i = 0; i < 4; ++i) {
                    v[i].x *= gv; v[i].y *= gv; v[i].z *= gv; v[i].w *= gv;
                    __stcs(po + (g2 * 4 + i) * 256, v[i]);
                }
            }
        }
        __syncthreads();   // protect smem reuse across tasks
    }
}

// ---------------------------------------------------------------------------
extern "C" void kernel_launch(void* const* d_in, const int* in_sizes, int n_in,
                              void* d_out, int out_size) {
    const float4* x  = (const float4*)d_in[0];
    const float*  W1 = (const float*)d_in[1];
    const float*  W2 = (const float*)d_in[2];
    float4* out = (float4*)d_out;

    se_init<<<1, 64>>>();
    se_persist<<<P_BLOCKS, TPB>>>(x, out, W1, W2);
}